// round 5
// baseline (speedup 1.0000x reference)
#include <cuda_runtime.h>
#include <cuda_bf16.h>

// NeuSSampler inverse-CDF importance sampling — dense-gather formulation v3.
// weights [R,128,1] f32, existing_bins [R,129] f32, nears [R,1], fars [R,1]
// -> out [R,65] f32.
//
// One warp per ray. Phase 1 builds the 129-entry CDF in registers (float4
// load + warp scan, histogram padding folded analytically). Phase 2 stages
// CDF + bin edges to shared memory (aligned STS.128). Phase 3 is a dense,
// branch-free gather: lane handles outputs j=lane and j=lane+32 (lane 0 also
// j=64) via a 7-step branchless binary search ladder over the smem CDF
// (early probes are warp-broadcasts), then one lerp. No divergent loops,
// perfectly coalesced output stores.

#define S_SAMP 128
#define NB 65
#define HIST_PAD 1e-5f
#define EPS_V 1e-5f
#define WARPS_PER_BLOCK 8
#define NTHREADS (WARPS_PER_BLOCK * 32)
#define INV_NB (1.0f / 65.0f)
#define SM_W 132   // padded row (129 used)

__global__ __launch_bounds__(NTHREADS)
void neus_sampler_kernel(const float* __restrict__ weights,
                         const float* __restrict__ ebins,
                         const float* __restrict__ nears,
                         const float* __restrict__ fars,
                         float* __restrict__ out,
                         int R)
{
    __shared__ float cdf_sm[WARPS_PER_BLOCK][SM_W];
    __shared__ float bin_sm[WARPS_PER_BLOCK][SM_W];

    const int warp = threadIdx.x >> 5;
    const int lane = threadIdx.x & 31;
    const int ray  = blockIdx.x * WARPS_PER_BLOCK + warp;
    if (ray >= R) return;

    // ---- 1. raw cumsum of 4 weights (512B-stride rows: float4 ok) ----
    const float4 wv = *reinterpret_cast<const float4*>(
        weights + (size_t)ray * S_SAMP + lane * 4);
    const float l0 = wv.x;
    const float l1 = l0 + wv.y;
    const float l2 = l1 + wv.z;
    const float l3 = l2 + wv.w;

    // ---- 2. warp inclusive scan over chunk sums ----
    float pre = l3;
    #pragma unroll
    for (int off = 1; off < 32; off <<= 1) {
        float v = __shfl_up_sync(0xffffffffu, pre, off);
        if (lane >= off) pre += v;
    }
    const float total_raw = __shfl_sync(0xffffffffu, pre, 31);
    const float excl      = pre - l3;

    // ---- 3. padding folded into one per-index step ----
    const float total_wp = total_raw + (float)S_SAMP * HIST_PAD;
    const float padding  = fmaxf(0.0f, EPS_V - total_wp);
    const float inv_wsum = __fdividef(1.0f, total_wp + padding);
    const float step     = HIST_PAD + padding * (1.0f / (float)S_SAMP);

    const int k = lane * 4;
    const float kf = (float)k;
    // cdf at indices k..k+4  (lane0: cdf[0] = 0 exactly)
    const float c0 = fmaf(kf,        step, excl     ) * inv_wsum;
    const float c1 = fmaf(kf + 1.0f, step, excl + l0) * inv_wsum;
    const float c2 = fmaf(kf + 2.0f, step, excl + l1) * inv_wsum;
    const float c3 = fmaf(kf + 3.0f, step, excl + l2) * inv_wsum;
    const float c4 = fmaf(kf + 4.0f, step, excl + l3) * inv_wsum;

    // ---- 4. bin edges (516B row stride -> scalar loads) ----
    const float* eb = ebins + (size_t)ray * (S_SAMP + 1) + k;
    const float b0 = __ldg(eb + 0);
    const float b1 = __ldg(eb + 1);
    const float b2 = __ldg(eb + 2);
    const float b3 = __ldg(eb + 3);

    // ---- 5. stage CDF + bins to smem (aligned 16B stores) ----
    float4 cv; cv.x = c0; cv.y = c1; cv.z = c2; cv.w = c3;
    *reinterpret_cast<float4*>(&cdf_sm[warp][k]) = cv;
    float4 bv; bv.x = b0; bv.y = b1; bv.z = b2; bv.w = b3;
    *reinterpret_cast<float4*>(&bin_sm[warp][k]) = bv;
    if (lane == 31) {
        cdf_sm[warp][S_SAMP] = c4;
        bin_sm[warp][S_SAMP] = __ldg(eb + 4);   // ebins[ray][128]
    }
    __syncwarp();

    const float nearv = nears[ray];
    const float dfn   = fars[ray] - nearv;
    float* orow = out + (size_t)ray * NB;
    const float* cw = cdf_sm[warp];
    const float* bw = bin_sm[warp];

    // ---- 6. dense branch-free gather: j = lane, lane+32, (lane0: 64) ----
    #pragma unroll
    for (int q = 0; q < 2; q++) {
        const int j   = lane + 32 * q;
        const float u = ((float)j + 0.5f) * INV_NB;
        int lo = 0;
        #pragma unroll
        for (int st = 64; st >= 1; st >>= 1)
            if (cw[lo + st] <= u) lo += st;
        // cdf[lo] <= u < cdf[lo+1]  (== reference searchsorted-right - 1)
        const float cg0 = cw[lo];
        const float cg1 = cw[lo + 1];
        const float bg0 = bw[lo];
        const float bg1 = bw[lo + 1];
        const float t   = (u - cg0) * __fdividef(1.0f, cg1 - cg0);
        const float bb  = fmaf(t, bg1 - bg0, bg0);
        orow[j] = fmaf(bb, dfn, nearv);
    }
    if (lane == 0) {
        const float u = 64.5f * INV_NB;
        int lo = 0;
        #pragma unroll
        for (int st = 64; st >= 1; st >>= 1)
            if (cw[lo + st] <= u) lo += st;
        const float cg0 = cw[lo];
        const float cg1 = cw[lo + 1];
        const float bg0 = bw[lo];
        const float bg1 = bw[lo + 1];
        const float t   = (u - cg0) * __fdividef(1.0f, cg1 - cg0);
        const float bb  = fmaf(t, bg1 - bg0, bg0);
        orow[64] = fmaf(bb, dfn, nearv);
    }
}

extern "C" void kernel_launch(void* const* d_in, const int* in_sizes, int n_in,
                              void* d_out, int out_size) {
    const float* weights = (const float*)d_in[0];
    const float* ebins   = (const float*)d_in[1];
    const float* nears   = (const float*)d_in[2];
    const float* fars    = (const float*)d_in[3];
    float* out = (float*)d_out;

    const int R = in_sizes[2];  // nears has R elements
    const int grid = (R + WARPS_PER_BLOCK - 1) / WARPS_PER_BLOCK;
    neus_sampler_kernel<<<grid, NTHREADS>>>(weights, ebins, nears, fars, out, R);
}